// round 10
// baseline (speedup 1.0000x reference)
#include <cuda_runtime.h>
#include <cuda_fp16.h>
#include <cstdint>

#define B_   8
#define C_   64
#define H_   128
#define W_   128
#define CE_  576
#define P_   (H_*W_)
#define OUP_ 128
#define EPSF 1e-5f

typedef unsigned long long ull;

// ---- scratch (device globals; no runtime allocation allowed) ----
__device__ __half g_ah[(size_t)B_*CE_*P_];  // 151 MB: relu(bn(dwconv)) fp16, gated in-place
__device__ __align__(16) __half g_wh[CE_*OUP_];  // fp16 weights, PRE-SWIZZLED chunks [36][4KB]
__device__ float g_stats[B_*C_*2];          // sum, sumsq per (b,c)
__device__ float g_gate[B_*C_*4];           // G0, G1, A1, B1 per (b,c)
__device__ float g_ep[OUP_*2];              // conv BN folded: scale, shift per o

static __device__ __forceinline__ float tanhfast(float x) {
    float y;
    asm("tanh.approx.f32 %0, %1;" : "=f"(y) : "f"(x));
    return y;
}

#define PK2F(d,a,b)  asm("mov.b64 %0, {%1, %2};" : "=l"(d) : "f"(a), "f"(b))
#define UPK2F(a,b,d) asm("mov.b64 {%0, %1}, %2;" : "=f"(a), "=f"(b) : "l"(d))
#define MUL2(d,a,b)  asm("mul.rn.f32x2 %0, %1, %2;" : "=l"(d) : "l"(a), "l"(b))
#define FMA2(d,a,b,c) asm("fma.rn.f32x2 %0, %1, %2, %3;" : "=l"(d) : "l"(a), "l"(b), "l"(c))

// ---------------- k1: depthwise conv (packed f32x2) + BN + ReLU + fp16 store + stats ----------------
__global__ __launch_bounds__(256) void k1_gen(
    const float* __restrict__ x,  const float* __restrict__ gw,
    const float* __restrict__ bg, const float* __restrict__ bb,
    const float* __restrict__ bm, const float* __restrict__ bv)
{
    int t = threadIdx.x;
    int rowblk = blockIdx.x, c = blockIdx.y, b = blockIdx.z;
    __shared__ float sx[18*130];
    __shared__ __align__(8) float2 swv2[81], ssc2[9], ssh2[9];
    __shared__ float red[16];

    const float* xp = x + (size_t)(b*C_ + c)*P_;
    for (int idx = t; idx < 18*130; idx += 256) {
        int rr = idx / 130, cc = idx - rr*130;
        int gh = rowblk*16 + rr - 1, gwc = cc - 1;
        float v = 0.f;
        if ((unsigned)gh < (unsigned)H_ && (unsigned)gwc < (unsigned)W_)
            v = xp[gh*W_ + gwc];
        sx[idx] = v;
    }
    int ce0 = c*9;
    if (t < 81) {
        float w = gw[ce0*9 + t];
        swv2[t] = make_float2(w, w);
    }
    if (t < 9) {
        float g = bg[ce0+t];
        float sc = g / sqrtf(bv[ce0+t] + EPSF);
        float sh = bb[ce0+t] - bm[ce0+t]*sc;
        ssc2[t] = make_float2(sc, sc);
        ssh2[t] = make_float2(sh, sh);
    }
    __syncthreads();

    int r = t >> 4, c8 = (t & 15) * 8;
    ull P0[9], P1[9], P2[9];
    {
        float xs0[10], xs1[10], xs2[10];
        #pragma unroll
        for (int i = 0; i < 10; i++) {
            xs0[i] = sx[(r  )*130 + c8 + i];
            xs1[i] = sx[(r+1)*130 + c8 + i];
            xs2[i] = sx[(r+2)*130 + c8 + i];
        }
        #pragma unroll
        for (int s = 0; s < 9; s++) {
            PK2F(P0[s], xs0[s], xs0[s+1]);
            PK2F(P1[s], xs1[s], xs1[s+1]);
            PK2F(P2[s], xs2[s], xs2[s+1]);
        }
    }
    float lsum = 0.f, lsq = 0.f;
    int gh0 = rowblk*16 + r;
    #pragma unroll
    for (int j = 0; j < 9; j++) {
        const ull* wj = reinterpret_cast<const ull*>(&swv2[j*9]);
        ull w0=wj[0], w1=wj[1], w2=wj[2], w3=wj[3], w4=wj[4];
        ull w5=wj[5], w6=wj[6], w7=wj[7], w8=wj[8];
        ull scq = *reinterpret_cast<const ull*>(&ssc2[j]);
        ull shq = *reinterpret_cast<const ull*>(&ssh2[j]);
        ull acc2[4];
        #pragma unroll
        for (int p = 0; p < 4; p++) {
            ull a;
            MUL2(a, P0[2*p  ], w0);
            FMA2(a, P0[2*p+1], w1, a);
            FMA2(a, P0[2*p+2], w2, a);
            FMA2(a, P1[2*p  ], w3, a);
            FMA2(a, P1[2*p+1], w4, a);
            FMA2(a, P1[2*p+2], w5, a);
            FMA2(a, P2[2*p  ], w6, a);
            FMA2(a, P2[2*p+1], w7, a);
            FMA2(a, P2[2*p+2], w8, a);
            FMA2(a, a, scq, shq);   // BN
            acc2[p] = a;
        }
        uint4 u;
        unsigned* up = reinterpret_cast<unsigned*>(&u);
        #pragma unroll
        for (int p = 0; p < 4; p++) {
            float v0, v1;
            UPK2F(v0, v1, acc2[p]);
            float a0 = fmaxf(v0, 0.f), a1 = fmaxf(v1, 0.f);
            lsum += a0; lsq = fmaf(a0, a0, lsq);
            lsum += a1; lsq = fmaf(a1, a1, lsq);
            __half2 h = __floats2half2_rn(a0, a1);
            up[p] = *reinterpret_cast<unsigned*>(&h);
        }
        __half* op = g_ah + ((size_t)(b*CE_ + ce0 + j)*H_ + gh0)*W_ + c8;
        *reinterpret_cast<uint4*>(op) = u;
    }
    #pragma unroll
    for (int off = 16; off; off >>= 1) {
        lsum += __shfl_down_sync(0xffffffffu, lsum, off);
        lsq  += __shfl_down_sync(0xffffffffu, lsq , off);
    }
    int wid = t >> 5, lane = t & 31;
    if (lane == 0) { red[wid] = lsum; red[wid+8] = lsq; }
    __syncthreads();
    if (t == 0) {
        float s = 0.f, q = 0.f;
        #pragma unroll
        for (int i = 0; i < 8; i++) { s += red[i]; q += red[i+8]; }
        atomicAdd(&g_stats[(b*C_+c)*2+0], s);
        atomicAdd(&g_stats[(b*C_+c)*2+1], q);
    }
}

// ---------------- k2: fold gate params (tanh form) ----------------
__global__ void k2_gate(const float* __restrict__ gn_w, const float* __restrict__ gn_b,
    const float* __restrict__ cw, const float* __restrict__ cb,
    const float* __restrict__ sw, const float* __restrict__ sb,
    const float* __restrict__ wadd_p)
{
    int t = threadIdx.x;
    if (t >= B_*C_) return;
    int c = t & (C_-1), cg = c & 7;
    float s = g_stats[t*2], q = g_stats[t*2+1];
    const float N = (float)(9*P_);
    float mean = s / N;
    float var  = fmaxf(q / N - mean*mean, 0.f);
    float inv  = 1.f / sqrtf(var + EPSF);
    float wadd = *wadd_p;
    float tc = cw[cg]*mean + cb[cg];
    float gC = 1.f / (1.f + __expf(-tc));
    float alpha = sw[cg]*gn_w[cg]*inv;
    float beta  = sw[cg]*(gn_b[cg] - mean*inv*gn_w[cg]) + sb[cg];
    float w2 = 1.f - wadd;
    g_gate[t*4+0] = wadd*gC + 0.5f*w2;  // G0
    g_gate[t*4+1] = 0.5f*w2;            // G1
    g_gate[t*4+2] = 0.5f*alpha;         // A1
    g_gate[t*4+3] = 0.5f*beta;          // B1
}

// ---------------- k2b: zero stats + W -> fp16 PRE-SWIZZLED chunks + fold conv BN ----------------
// chunk layout (4KB per 16-k chunk): byte off = o*32 + (((kq>>3)<<4) ^ ((o&4)<<2)) + (kq&7)*2
__global__ void k2b_prep(const float* __restrict__ cwv,
                         const float* __restrict__ g, const float* __restrict__ bb,
                         const float* __restrict__ m, const float* __restrict__ v)
{
    int idx = blockIdx.x*256 + threadIdx.x;
    if (idx < CE_*OUP_) {
        int o = idx / CE_, k = idx - o*CE_;
        int chunk = k >> 4, kq = k & 15;
        uint32_t off = (uint32_t)(o*32 + (((kq>>3)<<4) ^ ((o&4)<<2)) + (kq&7)*2);
        *reinterpret_cast<__half*>(reinterpret_cast<char*>(g_wh) + (size_t)chunk*4096 + off)
            = __float2half_rn(cwv[idx]);
    }
    if (blockIdx.x == 0) {
        int i = threadIdx.x;
        g_stats[i] = 0.f; g_stats[i+256] = 0.f;
        g_stats[i+512] = 0.f; g_stats[i+768] = 0.f;
        if (i < OUP_) {
            float sc = g[i] / sqrtf(v[i] + EPSF);
            g_ep[i*2]   = sc;
            g_ep[i*2+1] = bb[i] - m[i]*sc;
        }
    }
}

// gate transform on 8 packed halves (fp32 math)
static __device__ __forceinline__ uint4 gate8(uint4 u, float4 gp) {
    __half2* h = reinterpret_cast<__half2*>(&u);
    #pragma unroll
    for (int i = 0; i < 4; i++) {
        float2 f = __half22float2(h[i]);
        float th0 = tanhfast(fmaf(gp.z, f.x, gp.w));
        float th1 = tanhfast(fmaf(gp.z, f.y, gp.w));
        h[i] = __floats2half2_rn(f.x * fmaf(gp.y, th0, gp.x),
                                 f.y * fmaf(gp.y, th1, gp.x));
    }
    return u;
}

// ---------------- k1c: streaming in-place gate on g_ah ----------------
__global__ __launch_bounds__(256) void k1c_gate()
{
    int c = blockIdx.y, b = blockIdx.z;
    float4 gp = reinterpret_cast<const float4*>(g_gate)[b*C_ + c];
    size_t base = ((size_t)(b*CE_ + c*9))*P_;
    size_t idx = base + (size_t)blockIdx.x*2048 + threadIdx.x*8;
    uint4* p = reinterpret_cast<uint4*>(g_ah + idx);
    *p = gate8(*p, gp);
}

// ---------------- k3: fp16 mma.sync GEMM, TMA bulk-copy producer, 6-stage mbarrier pipeline ----------------
#define LDSM4(r0,r1,r2,r3,addr) \
    asm volatile("ldmatrix.sync.aligned.m8n8.x4.shared.b16 {%0,%1,%2,%3}, [%4];" \
        : "=r"(r0),"=r"(r1),"=r"(r2),"=r"(r3) : "r"(addr))
#define LDSM4T(r0,r1,r2,r3,addr) \
    asm volatile("ldmatrix.sync.aligned.m8n8.x4.trans.shared.b16 {%0,%1,%2,%3}, [%4];" \
        : "=r"(r0),"=r"(r1),"=r"(r2),"=r"(r3) : "r"(addr))
#define MMA16816(c, a, b) \
    asm volatile("mma.sync.aligned.m16n8k16.row.col.f32.f16.f16.f32 " \
        "{%0,%1,%2,%3}, {%4,%5,%6,%7}, {%8,%9}, {%0,%1,%2,%3};" \
        : "+f"(c[0]),"+f"(c[1]),"+f"(c[2]),"+f"(c[3]) \
        : "r"(a[0]),"r"(a[1]),"r"(a[2]),"r"(a[3]), "r"(b[0]),"r"(b[1]))
#define BULK(dst, src, sz, mbar) \
    asm volatile("cp.async.bulk.shared::cta.global.mbarrier::complete_tx::bytes " \
        "[%0], [%1], %2, [%3];" :: "r"(dst), "l"(src), "r"(sz), "r"(mbar) : "memory")
#define EXPECT_TX(mbar, bytes) \
    asm volatile("mbarrier.arrive.expect_tx.shared.b64 _, [%0], %1;" \
        :: "r"(mbar), "r"(bytes) : "memory")

static __device__ __forceinline__ void mbar_wait(uint32_t addr, uint32_t parity) {
    uint32_t done = 0;
    while (!done) {
        asm volatile("{\n\t.reg .pred p;\n\t"
            "mbarrier.try_wait.parity.acquire.cta.shared::cta.b64 p, [%1], %2, 0x989680;\n\t"
            "selp.b32 %0, 1, 0, p;\n\t}"
            : "=r"(done) : "r"(addr), "r"(parity) : "memory");
    }
}

static __device__ __forceinline__ uint32_t swoff(int row, int sel) {
    return (uint32_t)(row*32 + ((sel<<4) ^ ((row & 4) << 2)));
}

#define STAGE_B   8448          // smem footprint: 4096 (W) + 16*272 (B rows padded)
#define TX_BYTES  8192u         // actual copied bytes: 4096 (W) + 16*256 (B)
#define SMEM_DYN  (6*STAGE_B)   // 50688

__global__ __launch_bounds__(256, 2) void k3_mma(float* __restrict__ out)
{
    extern __shared__ __align__(16) char dyn[];
    __shared__ __align__(8) ull sBar[6];

    int t = threadIdx.x, lane = t & 31, warp = t >> 5;
    int m_base = (warp >> 2) * 64;
    int n_base = (warp & 3) * 32;
    int b = blockIdx.y, pos0 = blockIdx.x * 128;

    uint32_t stBase;
    asm("{ .reg .u64 tt; cvta.to.shared.u64 tt, %1; cvt.u32.u64 %0, tt; }"
        : "=r"(stBase) : "l"(dyn));
    uint32_t bar0;
    asm("{ .reg .u64 tt; cvta.to.shared.u64 tt, %1; cvt.u32.u64 %0, tt; }"
        : "=r"(bar0) : "l"(&sBar[0]));

    if (t == 0) {
        #pragma unroll
        for (int s = 0; s < 6; s++)
            asm volatile("mbarrier.init.shared.b64 [%0], %1;"
                         :: "r"(bar0 + s*8), "r"(1u) : "memory");
    }
    __syncthreads();

    const __half* aBase = g_ah + (size_t)b*CE_*P_ + pos0;
    const char* wBase = reinterpret_cast<const char*>(g_wh);

    float acc[4][4][4];
    #pragma unroll
    for (int i = 0; i < 4; i++)
        #pragma unroll
        for (int j = 0; j < 4; j++)
            #pragma unroll
            for (int k = 0; k < 4; k++) acc[i][j][k] = 0.f;

    uint32_t offA = swoff(m_base + (lane & 15), lane >> 4);
    int gq = lane >> 3, rq = lane & 7;
    int kL = (gq & 1)*8 + rq;
    int cBb = (n_base >> 3) + (gq >> 1);

    auto issue = [&](int kc) {
        int st = kc % 6;
        uint32_t sb = stBase + st*STAGE_B;
        uint32_t bar = bar0 + st*8;
        if (t == 0) EXPECT_TX(bar, TX_BYTES);
        if (t < 16)
            BULK(sb + 4096 + t*272, aBase + (size_t)(kc*16 + t)*P_, 256u, bar);
        else if (t == 16)
            BULK(sb, wBase + (size_t)kc*4096, 4096u, bar);
    };
    issue(0); issue(1); issue(2); issue(3); issue(4);

    for (int kc = 0; kc < 36; kc++) {
        int cur = kc % 6;
        mbar_wait(bar0 + cur*8, (uint32_t)((kc/6) & 1));
        __syncthreads();
        if (kc < 31) issue(kc + 5);
        uint32_t aW = stBase + cur*STAGE_B + offA;
        uint32_t aB2 = stBase + cur*STAGE_B + 4096;
        uint32_t afr[4][4], bfr[4][2];
        #pragma unroll
        for (int fm = 0; fm < 4; fm++)
            LDSM4(afr[fm][0], afr[fm][1], afr[fm][2], afr[fm][3], aW + fm*512);
        #pragma unroll
        for (int pr = 0; pr < 2; pr++) {
            uint32_t r0, r1, r2, r3;
            uint32_t off = (uint32_t)kL*272 + (uint32_t)(cBb + pr*2)*16;
            LDSM4T(r0, r1, r2, r3, aB2 + off);
            bfr[2*pr][0] = r0; bfr[2*pr][1] = r1;
            bfr[2*pr+1][0] = r2; bfr[2*pr+1][1] = r3;
        }
        #pragma unroll
        for (int fm = 0; fm < 4; fm++)
            #pragma unroll
            for (int fn = 0; fn < 4; fn++)
                MMA16816(acc[fm][fn], afr[fm], bfr[fn]);
    }

    // epilogue: BN + SiLU + store
    int g = lane >> 2, tc4 = lane & 3;
    #pragma unroll
    for (int fm = 0; fm < 4; fm++) {
        int r0 = m_base + 16*fm + g, r1 = r0 + 8;
        float sc0 = g_ep[r0*2], sh0 = g_ep[r0*2+1];
        float sc1 = g_ep[r1*2], sh1 = g_ep[r1*2+1];
        float* o0 = out + ((size_t)b*OUP_ + r0)*P_ + pos0 + n_base + 2*tc4;
        float* o1 = out + ((size_t)b*OUP_ + r1)*P_ + pos0 + n_base + 2*tc4;
        #pragma unroll
        for (int fn = 0; fn < 4; fn++) {
            float z0 = fmaf(acc[fm][fn][0], sc0, sh0);
            float z1 = fmaf(acc[fm][fn][1], sc0, sh0);
            float z2 = fmaf(acc[fm][fn][2], sc1, sh1);
            float z3 = fmaf(acc[fm][fn][3], sc1, sh1);
            float2 v0 = make_float2(z0/(1.f+__expf(-z0)), z1/(1.f+__expf(-z1)));
            float2 v1 = make_float2(z2/(1.f+__expf(-z2)), z3/(1.f+__expf(-z3)));
            *reinterpret_cast<float2*>(o0 + 8*fn) = v0;
            *reinterpret_cast<float2*>(o1 + 8*fn) = v1;
        }
    }
}

extern "C" void kernel_launch(void* const* d_in, const int* in_sizes, int n_in,
                              void* d_out, int out_size)
{
    const float* x      = (const float*)d_in[0];
    const float* gen_w  = (const float*)d_in[1];
    const float* bg     = (const float*)d_in[2];
    const float* bb     = (const float*)d_in[3];
    const float* bm     = (const float*)d_in[4];
    const float* bv     = (const float*)d_in[5];
    const float* gn_w   = (const float*)d_in[6];
    const float* gn_b   = (const float*)d_in[7];
    const float* cw     = (const float*)d_in[8];
    const float* cb     = (const float*)d_in[9];
    const float* sw     = (const float*)d_in[10];
    const float* sb     = (const float*)d_in[11];
    const float* wadd   = (const float*)d_in[12];
    const float* conv_w = (const float*)d_in[13];
    const float* cbg    = (const float*)d_in[14];
    const float* cbb    = (const float*)d_in[15];
    const float* cbm    = (const float*)d_in[16];
    const float* cbv    = (const float*)d_in[17];
    float* out = (float*)d_out;

    cudaFuncSetAttribute(k3_mma, cudaFuncAttributeMaxDynamicSharedMemorySize, SMEM_DYN);

    k2b_prep<<<(CE_*OUP_ + 255)/256, 256>>>(conv_w, cbg, cbb, cbm, cbv);  // also zeros stats
    k1_gen<<<dim3(8, C_, B_), 256>>>(x, gen_w, bg, bb, bm, bv);
    k2_gate<<<1, 512>>>(gn_w, gn_b, cw, cb, sw, sb, wadd);
    k1c_gate<<<dim3(72, C_, B_), 256>>>();
    k3_mma<<<dim3(P_/128, B_), 256, SMEM_DYN>>>(out);
}

// round 11
// speedup vs baseline: 1.2344x; 1.2344x over previous
#include <cuda_runtime.h>
#include <cuda_fp16.h>
#include <cstdint>

#define B_   8
#define C_   64
#define H_   128
#define W_   128
#define CE_  576
#define P_   (H_*W_)
#define OUP_ 128
#define EPSF 1e-5f

typedef unsigned long long ull;

// ---- scratch (device globals; no runtime allocation allowed) ----
// g_ah layout: [b][pb(128)][chunk(36)][4096B]  where 4KB chunk = 16 k-rows x 256B,
// each row's sixteen 16B units permuted: unit s = (cc&8)|((cc^kk)&7)
__device__ __align__(16) __half g_ah[(size_t)B_*CE_*P_];
__device__ __align__(16) __half g_wh[CE_*OUP_];  // fp16 weights, PRE-SWIZZLED chunks [36][4KB]
__device__ float g_stats[B_*C_*2];          // sum, sumsq per (b,c)
__device__ float g_gate[B_*C_*4];           // G0, G1, A1, B1 per (b,c)
__device__ float g_ep[OUP_*2];              // conv BN folded: scale, shift per o

static __device__ __forceinline__ float tanhfast(float x) {
    float y;
    asm("tanh.approx.f32 %0, %1;" : "=f"(y) : "f"(x));
    return y;
}

#define PK2F(d,a,b)  asm("mov.b64 %0, {%1, %2};" : "=l"(d) : "f"(a), "f"(b))
#define UPK2F(a,b,d) asm("mov.b64 {%0, %1}, %2;" : "=f"(a), "=f"(b) : "l"(d))
#define MUL2(d,a,b)  asm("mul.rn.f32x2 %0, %1, %2;" : "=l"(d) : "l"(a), "l"(b))
#define FMA2(d,a,b,c) asm("fma.rn.f32x2 %0, %1, %2, %3;" : "=l"(d) : "l"(a), "l"(b), "l"(c))

// ---------------- k1: depthwise conv (packed f32x2) + BN + ReLU + swizzled fp16 store + stats ----------------
__global__ __launch_bounds__(256) void k1_gen(
    const float* __restrict__ x,  const float* __restrict__ gw,
    const float* __restrict__ bg, const float* __restrict__ bb,
    const float* __restrict__ bm, const float* __restrict__ bv)
{
    int t = threadIdx.x;
    int rowblk = blockIdx.x, c = blockIdx.y, b = blockIdx.z;
    __shared__ float sx[18*130];
    __shared__ __align__(8) float2 swv2[81], ssc2[9], ssh2[9];
    __shared__ float red[16];

    const float* xp = x + (size_t)(b*C_ + c)*P_;
    for (int idx = t; idx < 18*130; idx += 256) {
        int rr = idx / 130, cc = idx - rr*130;
        int gh = rowblk*16 + rr - 1, gwc = cc - 1;
        float v = 0.f;
        if ((unsigned)gh < (unsigned)H_ && (unsigned)gwc < (unsigned)W_)
            v = xp[gh*W_ + gwc];
        sx[idx] = v;
    }
    int ce0 = c*9;
    if (t < 81) {
        float w = gw[ce0*9 + t];
        swv2[t] = make_float2(w, w);
    }
    if (t < 9) {
        float g = bg[ce0+t];
        float sc = g / sqrtf(bv[ce0+t] + EPSF);
        float sh = bb[ce0+t] - bm[ce0+t]*sc;
        ssc2[t] = make_float2(sc, sc);
        ssh2[t] = make_float2(sh, sh);
    }
    __syncthreads();

    int r = t >> 4, cc16 = t & 15, c8 = cc16 * 8;
    ull P0[9], P1[9], P2[9];
    {
        float xs0[10], xs1[10], xs2[10];
        #pragma unroll
        for (int i = 0; i < 10; i++) {
            xs0[i] = sx[(r  )*130 + c8 + i];
            xs1[i] = sx[(r+1)*130 + c8 + i];
            xs2[i] = sx[(r+2)*130 + c8 + i];
        }
        #pragma unroll
        for (int s = 0; s < 9; s++) {
            PK2F(P0[s], xs0[s], xs0[s+1]);
            PK2F(P1[s], xs1[s], xs1[s+1]);
            PK2F(P2[s], xs2[s], xs2[s+1]);
        }
    }
    float lsum = 0.f, lsq = 0.f;
    int gh0 = rowblk*16 + r;   // = pb
    char* pbBase = reinterpret_cast<char*>(g_ah) +
                   (((size_t)(b*128 + gh0)*36) << 12);
    #pragma unroll
    for (int j = 0; j < 9; j++) {
        const ull* wj = reinterpret_cast<const ull*>(&swv2[j*9]);
        ull w0=wj[0], w1=wj[1], w2=wj[2], w3=wj[3], w4=wj[4];
        ull w5=wj[5], w6=wj[6], w7=wj[7], w8=wj[8];
        ull scq = *reinterpret_cast<const ull*>(&ssc2[j]);
        ull shq = *reinterpret_cast<const ull*>(&ssh2[j]);
        ull acc2[4];
        #pragma unroll
        for (int p = 0; p < 4; p++) {
            ull a;
            MUL2(a, P0[2*p  ], w0);
            FMA2(a, P0[2*p+1], w1, a);
            FMA2(a, P0[2*p+2], w2, a);
            FMA2(a, P1[2*p  ], w3, a);
            FMA2(a, P1[2*p+1], w4, a);
            FMA2(a, P1[2*p+2], w5, a);
            FMA2(a, P2[2*p  ], w6, a);
            FMA2(a, P2[2*p+1], w7, a);
            FMA2(a, P2[2*p+2], w8, a);
            FMA2(a, a, scq, shq);   // BN
            acc2[p] = a;
        }
        uint4 u;
        unsigned* up = reinterpret_cast<unsigned*>(&u);
        #pragma unroll
        for (int p = 0; p < 4; p++) {
            float v0, v1;
            UPK2F(v0, v1, acc2[p]);
            float a0 = fmaxf(v0, 0.f), a1 = fmaxf(v1, 0.f);
            lsum += a0; lsq = fmaf(a0, a0, lsq);
            lsum += a1; lsq = fmaf(a1, a1, lsq);
            __half2 h = __floats2half2_rn(a0, a1);
            up[p] = *reinterpret_cast<unsigned*>(&h);
        }
        int ce = ce0 + j;
        int ch = ce >> 4, kk = ce & 15;
        int s16 = (cc16 & 8) | ((cc16 ^ kk) & 7);
        *reinterpret_cast<uint4*>(pbBase + ((size_t)ch << 12) + kk*256 + s16*16) = u;
    }
    #pragma unroll
    for (int off = 16; off; off >>= 1) {
        lsum += __shfl_down_sync(0xffffffffu, lsum, off);
        lsq  += __shfl_down_sync(0xffffffffu, lsq , off);
    }
    int wid = t >> 5, lane = t & 31;
    if (lane == 0) { red[wid] = lsum; red[wid+8] = lsq; }
    __syncthreads();
    if (t == 0) {
        float s = 0.f, q = 0.f;
        #pragma unroll
        for (int i = 0; i < 8; i++) { s += red[i]; q += red[i+8]; }
        atomicAdd(&g_stats[(b*C_+c)*2+0], s);
        atomicAdd(&g_stats[(b*C_+c)*2+1], q);
    }
}

// ---------------- k2: fold gate params (tanh form) ----------------
__global__ void k2_gate(const float* __restrict__ gn_w, const float* __restrict__ gn_b,
    const float* __restrict__ cw, const float* __restrict__ cb,
    const float* __restrict__ sw, const float* __restrict__ sb,
    const float* __restrict__ wadd_p)
{
    int t = threadIdx.x;
    if (t >= B_*C_) return;
    int c = t & (C_-1), cg = c & 7;
    float s = g_stats[t*2], q = g_stats[t*2+1];
    const float N = (float)(9*P_);
    float mean = s / N;
    float var  = fmaxf(q / N - mean*mean, 0.f);
    float inv  = 1.f / sqrtf(var + EPSF);
    float wadd = *wadd_p;
    float tc = cw[cg]*mean + cb[cg];
    float gC = 1.f / (1.f + __expf(-tc));
    float alpha = sw[cg]*gn_w[cg]*inv;
    float beta  = sw[cg]*(gn_b[cg] - mean*inv*gn_w[cg]) + sb[cg];
    float w2 = 1.f - wadd;
    g_gate[t*4+0] = wadd*gC + 0.5f*w2;  // G0
    g_gate[t*4+1] = 0.5f*w2;            // G1
    g_gate[t*4+2] = 0.5f*alpha;         // A1
    g_gate[t*4+3] = 0.5f*beta;          // B1
}

// ---------------- k2b: zero stats + W -> fp16 PRE-SWIZZLED chunks + fold conv BN ----------------
__global__ void k2b_prep(const float* __restrict__ cwv,
                         const float* __restrict__ g, const float* __restrict__ bb,
                         const float* __restrict__ m, const float* __restrict__ v)
{
    int idx = blockIdx.x*256 + threadIdx.x;
    if (idx < CE_*OUP_) {
        int o = idx / CE_, k = idx - o*CE_;
        int chunk = k >> 4, kq = k & 15;
        uint32_t off = (uint32_t)(o*32 + (((kq>>3)<<4) ^ ((o&4)<<2)) + (kq&7)*2);
        *reinterpret_cast<__half*>(reinterpret_cast<char*>(g_wh) + (size_t)chunk*4096 + off)
            = __float2half_rn(cwv[idx]);
    }
    if (blockIdx.x == 0) {
        int i = threadIdx.x;
        g_stats[i] = 0.f; g_stats[i+256] = 0.f;
        g_stats[i+512] = 0.f; g_stats[i+768] = 0.f;
        if (i < OUP_) {
            float sc = g[i] / sqrtf(v[i] + EPSF);
            g_ep[i*2]   = sc;
            g_ep[i*2+1] = bb[i] - m[i]*sc;
        }
    }
}

// gate transform on 8 packed halves (fp32 math)
static __device__ __forceinline__ uint4 gate8(uint4 u, float4 gp) {
    __half2* h = reinterpret_cast<__half2*>(&u);
    #pragma unroll
    for (int i = 0; i < 4; i++) {
        float2 f = __half22float2(h[i]);
        float th0 = tanhfast(fmaf(gp.z, f.x, gp.w));
        float th1 = tanhfast(fmaf(gp.z, f.y, gp.w));
        h[i] = __floats2half2_rn(f.x * fmaf(gp.y, th0, gp.x),
                                 f.y * fmaf(gp.y, th1, gp.x));
    }
    return u;
}

// ---------------- k1c: streaming in-place gate on g_ah (new layout) ----------------
// grid (36 ch, 128 pb, 8 b), block 256: each block gates one 4KB chunk
__global__ __launch_bounds__(256) void k1c_gate()
{
    int t = threadIdx.x;
    int ch = blockIdx.x, pb = blockIdx.y, b = blockIdx.z;
    int ce = ch*16 + (t >> 4);
    int c = ce / 9;
    float4 gp = reinterpret_cast<const float4*>(g_gate)[b*C_ + c];
    char* p = reinterpret_cast<char*>(g_ah) +
              (((size_t)(b*128 + pb)*36 + ch) << 12) + t*16;
    uint4* q = reinterpret_cast<uint4*>(p);
    *q = gate8(*q, gp);
}

// ---------------- k3: fp16 mma.sync GEMM, 2x4KB bulk-copy producer, 6-stage mbarrier pipeline ----------------
#define LDSM4(r0,r1,r2,r3,addr) \
    asm volatile("ldmatrix.sync.aligned.m8n8.x4.shared.b16 {%0,%1,%2,%3}, [%4];" \
        : "=r"(r0),"=r"(r1),"=r"(r2),"=r"(r3) : "r"(addr))
#define LDSM4T(r0,r1,r2,r3,addr) \
    asm volatile("ldmatrix.sync.aligned.m8n8.x4.trans.shared.b16 {%0,%1,%2,%3}, [%4];" \
        : "=r"(r0),"=r"(r1),"=r"(r2),"=r"(r3) : "r"(addr))
#define MMA16816(c, a, b) \
    asm volatile("mma.sync.aligned.m16n8k16.row.col.f32.f16.f16.f32 " \
        "{%0,%1,%2,%3}, {%4,%5,%6,%7}, {%8,%9}, {%0,%1,%2,%3};" \
        : "+f"(c[0]),"+f"(c[1]),"+f"(c[2]),"+f"(c[3]) \
        : "r"(a[0]),"r"(a[1]),"r"(a[2]),"r"(a[3]), "r"(b[0]),"r"(b[1]))
#define BULK(dst, src, sz, mbar) \
    asm volatile("cp.async.bulk.shared::cta.global.mbarrier::complete_tx::bytes " \
        "[%0], [%1], %2, [%3];" :: "r"(dst), "l"(src), "r"(sz), "r"(mbar) : "memory")
#define EXPECT_TX(mbar, bytes) \
    asm volatile("mbarrier.arrive.expect_tx.shared.b64 _, [%0], %1;" \
        :: "r"(mbar), "r"(bytes) : "memory")

static __device__ __forceinline__ void mbar_wait(uint32_t addr, uint32_t parity) {
    uint32_t done = 0;
    while (!done) {
        asm volatile("{\n\t.reg .pred p;\n\t"
            "mbarrier.try_wait.parity.acquire.cta.shared::cta.b64 p, [%1], %2, 0x989680;\n\t"
            "selp.b32 %0, 1, 0, p;\n\t}"
            : "=r"(done) : "r"(addr), "r"(parity) : "memory");
    }
}

static __device__ __forceinline__ uint32_t swoff(int row, int sel) {
    return (uint32_t)(row*32 + ((sel<<4) ^ ((row & 4) << 2)));
}

#define STAGE_B   8192          // 4096 (W) + 4096 (B, 16 rows x 256B, swizzled in gmem)
#define SMEM_DYN  (6*STAGE_B)   // 49152

__global__ __launch_bounds__(256, 2) void k3_mma(float* __restrict__ out)
{
    extern __shared__ __align__(16) char dyn[];
    __shared__ __align__(8) ull sBar[6];

    int t = threadIdx.x, lane = t & 31, warp = t >> 5;
    int m_base = (warp >> 2) * 64;
    int n_base = (warp & 3) * 32;
    int b = blockIdx.y, pb = blockIdx.x;
    int pos0 = pb * 128;

    uint32_t stBase;
    asm("{ .reg .u64 tt; cvta.to.shared.u64 tt, %1; cvt.u32.u64 %0, tt; }"
        : "=r"(stBase) : "l"(dyn));
    uint32_t bar0;
    asm("{ .reg .u64 tt; cvta.to.shared.u64 tt, %1; cvt.u32.u64 %0, tt; }"
        : "=r"(bar0) : "l"(&sBar[0]));

    if (t == 0) {
        #pragma unroll
        for (int s = 0; s < 6; s++)
            asm volatile("mbarrier.init.shared.b64 [%0], %1;"
                         :: "r"(bar0 + s*8), "r"(1u) : "memory");
    }
    __syncthreads();

    const char* aBytes = reinterpret_cast<const char*>(g_ah) +
                         (((size_t)(b*128 + pb)*36) << 12);
    const char* wBase = reinterpret_cast<const char*>(g_wh);

    float acc[4][4][4];
    #pragma unroll
    for (int i = 0; i < 4; i++)
        #pragma unroll
        for (int j = 0; j < 4; j++)
            #pragma unroll
            for (int k = 0; k < 4; k++) acc[i][j][k] = 0.f;

    uint32_t offA = swoff(m_base + (lane & 15), lane >> 4);
    int gq = lane >> 3, rq = lane & 7;
    int kL = (gq & 1)*8 + rq;
    int cBb = (n_base >> 3) + (gq >> 1);

    auto issue = [&](int kc) {
        int st = kc % 6;
        uint32_t sb = stBase + st*STAGE_B;
        uint32_t bar = bar0 + st*8;
        if (t == 0) {
            EXPECT_TX(bar, (uint32_t)STAGE_B);
            BULK(sb + 4096, aBytes + ((size_t)kc << 12), 4096u, bar);
        } else if (t == 1) {
            BULK(sb, wBase + ((size_t)kc << 12), 4096u, bar);
        }
    };
    issue(0); issue(1); issue(2); issue(3); issue(4);

    for (int kc = 0; kc < 36; kc++) {
        int cur = kc % 6;
        mbar_wait(bar0 + cur*8, (uint32_t)((kc/6) & 1));
        __syncthreads();
        if (kc < 31) issue(kc + 5);
        uint32_t aW = stBase + cur*STAGE_B + offA;
        uint32_t aB2 = stBase + cur*STAGE_B + 4096;
        uint32_t afr[4][4], bfr[4][2];
        #pragma unroll
        for (int fm = 0; fm < 4; fm++)
            LDSM4(afr[fm][0], afr[fm][1], afr[fm][2], afr[fm][3], aW + fm*512);
        #pragma unroll
        for (int pr = 0; pr < 2; pr++) {
            uint32_t r0, r1, r2, r3;
            int cc = cBb + pr*2;
            int s16 = (cc & 8) | ((cc ^ kL) & 7);
            uint32_t off = (uint32_t)kL*256 + (uint32_t)s16*16;
            LDSM4T(r0, r1, r2, r3, aB2 + off);
            bfr[2*pr][0] = r0; bfr[2*pr][1] = r1;
            bfr[2*pr+1][0] = r2; bfr[2*pr+1][1] = r3;
        }
        #pragma unroll
        for (int fm = 0; fm < 4; fm++)
            #pragma unroll
            for (int fn = 0; fn < 4; fn++)
                MMA16816(acc[fm][fn], afr[fm], bfr[fn]);
    }

    // epilogue: BN + SiLU + store
    int g = lane >> 2, tc4 = lane & 3;
    #pragma unroll
    for (int fm = 0; fm < 4; fm++) {
        int r0 = m_base + 16*fm + g, r1 = r0 + 8;
        float sc0 = g_ep[r0*2], sh0 = g_ep[r0*2+1];
        float sc1 = g_ep[r1*2], sh1 = g_ep[r1*2+1];
        float* o0 = out + ((size_t)b*OUP_ + r0)*P_ + pos0 + n_base + 2*tc4;
        float* o1 = out + ((size_t)b*OUP_ + r1)*P_ + pos0 + n_base + 2*tc4;
        #pragma unroll
        for (int fn = 0; fn < 4; fn++) {
            float z0 = fmaf(acc[fm][fn][0], sc0, sh0);
            float z1 = fmaf(acc[fm][fn][1], sc0, sh0);
            float z2 = fmaf(acc[fm][fn][2], sc1, sh1);
            float z3 = fmaf(acc[fm][fn][3], sc1, sh1);
            float2 v0 = make_float2(z0/(1.f+__expf(-z0)), z1/(1.f+__expf(-z1)));
            float2 v1 = make_float2(z2/(1.f+__expf(-z2)), z3/(1.f+__expf(-z3)));
            *reinterpret_cast<float2*>(o0 + 8*fn) = v0;
            *reinterpret_cast<float2*>(o1 + 8*fn) = v1;
        }
    }
}

extern "C" void kernel_launch(void* const* d_in, const int* in_sizes, int n_in,
                              void* d_out, int out_size)
{
    const float* x      = (const float*)d_in[0];
    const float* gen_w  = (const float*)d_in[1];
    const float* bg     = (const float*)d_in[2];
    const float* bb     = (const float*)d_in[3];
    const float* bm     = (const float*)d_in[4];
    const float* bv     = (const float*)d_in[5];
    const float* gn_w   = (const float*)d_in[6];
    const float* gn_b   = (const float*)d_in[7];
    const float* cw     = (const float*)d_in[8];
    const float* cb     = (const float*)d_in[9];
    const float* sw     = (const float*)d_in[10];
    const float* sb     = (const float*)d_in[11];
    const float* wadd   = (const float*)d_in[12];
    const float* conv_w = (const float*)d_in[13];
    const float* cbg    = (const float*)d_in[14];
    const float* cbb    = (const float*)d_in[15];
    const float* cbm    = (const float*)d_in[16];
    const float* cbv    = (const float*)d_in[17];
    float* out = (float*)d_out;

    cudaFuncSetAttribute(k3_mma, cudaFuncAttributeMaxDynamicSharedMemorySize, SMEM_DYN);

    k2b_prep<<<(CE_*OUP_ + 255)/256, 256>>>(conv_w, cbg, cbb, cbm, cbv);  // also zeros stats
    k1_gen<<<dim3(8, C_, B_), 256>>>(x, gen_w, bg, bb, bm, bv);
    k2_gate<<<1, 512>>>(gn_w, gn_b, cw, cb, sw, sb, wadd);
    k1c_gate<<<dim3(36, 128, B_), 256>>>();
    k3_mma<<<dim3(P_/128, B_), 256, SMEM_DYN>>>(out);
}